// round 1
// baseline (speedup 1.0000x reference)
#include <cuda_runtime.h>
#include <cstdint>

#define B_  8
#define N_  4096
#define M_  2048
#define D_  256
#define DV_ 256
#define INV_T (1.0f / 16.0f)
#define MASK_FILL -1e9f

// ---------------------------------------------------------------------------
// K1: S[b,n,m] = mask ? dot(q[b,n,:], k[b,m,:]) / 16 : -1e9
// C = A * B^T tiled SGEMM, 128x128 tile, BK=8, 8x8 per thread, 256 threads.
// Writes directly into the attn region of d_out.
// ---------------------------------------------------------------------------
__global__ void __launch_bounds__(256) qk_mask_kernel(
    const float* __restrict__ q, const float* __restrict__ kmat,
    const int* __restrict__ mask, float* __restrict__ attn)
{
    const int b  = blockIdx.z;
    const int n0 = blockIdx.y * 128;
    const int m0 = blockIdx.x * 128;

    const float* Q = q    + ((size_t)b * N_ + n0) * D_;
    const float* K = kmat + ((size_t)b * M_ + m0) * D_;

    __shared__ float As[8][128];
    __shared__ float Bs[8][128];

    const int tid  = threadIdx.x;
    const int lrow = tid >> 1;          // 0..127
    const int lcol = (tid & 1) << 2;    // 0 or 4
    const int ty   = tid >> 4;          // 0..15
    const int tx   = tid & 15;          // 0..15

    float acc[8][8];
#pragma unroll
    for (int i = 0; i < 8; i++)
#pragma unroll
        for (int j = 0; j < 8; j++) acc[i][j] = 0.f;

    for (int kt = 0; kt < D_; kt += 8) {
        float4 a4 = *(const float4*)(Q + (size_t)lrow * D_ + kt + lcol);
        float4 b4 = *(const float4*)(K + (size_t)lrow * D_ + kt + lcol);
        __syncthreads();
        As[lcol + 0][lrow] = a4.x; As[lcol + 1][lrow] = a4.y;
        As[lcol + 2][lrow] = a4.z; As[lcol + 3][lrow] = a4.w;
        Bs[lcol + 0][lrow] = b4.x; Bs[lcol + 1][lrow] = b4.y;
        Bs[lcol + 2][lrow] = b4.z; Bs[lcol + 3][lrow] = b4.w;
        __syncthreads();
#pragma unroll
        for (int kk = 0; kk < 8; kk++) {
            float a[8], bb[8];
#pragma unroll
            for (int i = 0; i < 8; i++) a[i]  = As[kk][ty * 8 + i];
#pragma unroll
            for (int j = 0; j < 8; j++) bb[j] = Bs[kk][tx * 8 + j];
#pragma unroll
            for (int i = 0; i < 8; i++)
#pragma unroll
                for (int j = 0; j < 8; j++) acc[i][j] += a[i] * bb[j];
        }
    }

    float*     orow = attn + ((size_t)b * N_ + n0) * M_ + m0;
    const int* mrow = mask + ((size_t)b * N_ + n0) * M_ + m0;
#pragma unroll
    for (int i = 0; i < 8; i++) {
        const int row = ty * 8 + i;
        const int col = tx * 8;
        const int4* m4 = (const int4*)(mrow + (size_t)row * M_ + col);
        int4 mlo = m4[0];
        int4 mhi = m4[1];
        float4 r0, r1;
        r0.x = mlo.x ? acc[i][0] * INV_T : MASK_FILL;
        r0.y = mlo.y ? acc[i][1] * INV_T : MASK_FILL;
        r0.z = mlo.z ? acc[i][2] * INV_T : MASK_FILL;
        r0.w = mlo.w ? acc[i][3] * INV_T : MASK_FILL;
        r1.x = mhi.x ? acc[i][4] * INV_T : MASK_FILL;
        r1.y = mhi.y ? acc[i][5] * INV_T : MASK_FILL;
        r1.z = mhi.z ? acc[i][6] * INV_T : MASK_FILL;
        r1.w = mhi.w ? acc[i][7] * INV_T : MASK_FILL;
        float4* o4 = (float4*)(orow + (size_t)row * M_ + col);
        o4[0] = r0;
        o4[1] = r1;
    }
}

// ---------------------------------------------------------------------------
// K2: per-row fused double softmax + add, in place on the attn region.
//   attn[row] = softmax(attn[row]) + softmax(oa[row])
// One block (256 threads) per (b,n) row of length M=2048; 8 elems/thread.
// ---------------------------------------------------------------------------
__global__ void __launch_bounds__(256) softmax_add_kernel(
    const float* __restrict__ oa, float* __restrict__ attn)
{
    const size_t row = blockIdx.x;          // b*N + n
    float*       s = attn + row * M_;
    const float* o = oa   + row * M_;

    const int tid  = threadIdx.x;
    const int lane = tid & 31;
    const int warp = tid >> 5;

    float sv[8], ov[8];
#pragma unroll
    for (int i = 0; i < 8; i++) {
        sv[i] = s[tid + i * 256];
        ov[i] = o[tid + i * 256];
    }

    float smax = -3.4e38f, omax = -3.4e38f;
#pragma unroll
    for (int i = 0; i < 8; i++) {
        smax = fmaxf(smax, sv[i]);
        omax = fmaxf(omax, ov[i]);
    }
#pragma unroll
    for (int off = 16; off > 0; off >>= 1) {
        smax = fmaxf(smax, __shfl_xor_sync(0xffffffffu, smax, off));
        omax = fmaxf(omax, __shfl_xor_sync(0xffffffffu, omax, off));
    }

    __shared__ float red[4][8];
    if (lane == 0) { red[0][warp] = smax; red[1][warp] = omax; }
    __syncthreads();
#pragma unroll
    for (int w = 0; w < 8; w++) {
        smax = fmaxf(smax, red[0][w]);
        omax = fmaxf(omax, red[1][w]);
    }

    float ssum = 0.f, osum = 0.f;
#pragma unroll
    for (int i = 0; i < 8; i++) {
        sv[i] = __expf(sv[i] - smax);
        ov[i] = __expf(ov[i] - omax);
        ssum += sv[i];
        osum += ov[i];
    }
#pragma unroll
    for (int off = 16; off > 0; off >>= 1) {
        ssum += __shfl_xor_sync(0xffffffffu, ssum, off);
        osum += __shfl_xor_sync(0xffffffffu, osum, off);
    }
    if (lane == 0) { red[2][warp] = ssum; red[3][warp] = osum; }
    __syncthreads();
    ssum = 0.f; osum = 0.f;
#pragma unroll
    for (int w = 0; w < 8; w++) {
        ssum += red[2][w];
        osum += red[3][w];
    }
    const float sinv = 1.0f / ssum;
    const float oinv = 1.0f / osum;

#pragma unroll
    for (int i = 0; i < 8; i++)
        s[tid + i * 256] = sv[i] * sinv + ov[i] * oinv;
}

// ---------------------------------------------------------------------------
// K3: out[b,n,c] = sum_m attn[b,n,m] * v[b,m,c]
// C = A * B tiled SGEMM, 128x128 tile, BK=8, 8x8 per thread, 256 threads.
// ---------------------------------------------------------------------------
__global__ void __launch_bounds__(256) av_kernel(
    const float* __restrict__ attn, const float* __restrict__ v,
    float* __restrict__ out)
{
    const int b  = blockIdx.z;
    const int n0 = blockIdx.y * 128;
    const int c0 = blockIdx.x * 128;

    const float* A  = attn + ((size_t)b * N_ + n0) * M_;
    const float* Bv = v    + (size_t)b * M_ * DV_ + c0;

    __shared__ float As[8][128];
    __shared__ float Bs[8][128];

    const int tid  = threadIdx.x;
    const int lrow = tid >> 1;          // 0..127  (A tile row)
    const int lcol = (tid & 1) << 2;    // 0 or 4  (A tile k-col)
    const int brow = tid >> 5;          // 0..7    (B tile k-row)
    const int bcol = (tid & 31) << 2;   // 0..124  (B tile col)
    const int ty   = tid >> 4;
    const int tx   = tid & 15;

    float acc[8][8];
#pragma unroll
    for (int i = 0; i < 8; i++)
#pragma unroll
        for (int j = 0; j < 8; j++) acc[i][j] = 0.f;

    for (int kt = 0; kt < M_; kt += 8) {
        float4 a4 = *(const float4*)(A  + (size_t)lrow * M_ + kt + lcol);
        float4 b4 = *(const float4*)(Bv + (size_t)(kt + brow) * DV_ + bcol);
        __syncthreads();
        As[lcol + 0][lrow] = a4.x; As[lcol + 1][lrow] = a4.y;
        As[lcol + 2][lrow] = a4.z; As[lcol + 3][lrow] = a4.w;
        *(float4*)&Bs[brow][bcol] = b4;
        __syncthreads();
#pragma unroll
        for (int kk = 0; kk < 8; kk++) {
            float a[8], bb[8];
#pragma unroll
            for (int i = 0; i < 8; i++) a[i]  = As[kk][ty * 8 + i];
#pragma unroll
            for (int j = 0; j < 8; j++) bb[j] = Bs[kk][tx * 8 + j];
#pragma unroll
            for (int i = 0; i < 8; i++)
#pragma unroll
                for (int j = 0; j < 8; j++) acc[i][j] += a[i] * bb[j];
        }
    }

    float* orow = out + ((size_t)b * N_ + n0) * DV_ + c0;
#pragma unroll
    for (int i = 0; i < 8; i++) {
        const int row = ty * 8 + i;
        const int col = tx * 8;
        float4 r0 = make_float4(acc[i][0], acc[i][1], acc[i][2], acc[i][3]);
        float4 r1 = make_float4(acc[i][4], acc[i][5], acc[i][6], acc[i][7]);
        float4* o4 = (float4*)(orow + (size_t)row * DV_ + col);
        o4[0] = r0;
        o4[1] = r1;
    }
}

// ---------------------------------------------------------------------------
extern "C" void kernel_launch(void* const* d_in, const int* in_sizes, int n_in,
                              void* d_out, int out_size)
{
    const float* q    = (const float*)d_in[0];
    const float* k    = (const float*)d_in[1];
    const float* v    = (const float*)d_in[2];
    const float* oa   = (const float*)d_in[3];
    const int*   mask = (const int*)d_in[4];
    // d_in[5] = feature; always truthy for these shapes (N != M makes the
    // transpose branch shape-invalid in the reference), so it is ignored.

    float* out  = (float*)d_out;                        // [B, N, DV]
    float* attn = out + (size_t)B_ * N_ * DV_;          // [B, N, M]

    // K1: masked scaled logits into attn region (in-place staging).
    qk_mask_kernel<<<dim3(M_ / 128, N_ / 128, B_), 256>>>(q, k, mask, attn);
    // K2: attn = softmax(logits) + softmax(oa), in place.
    softmax_add_kernel<<<B_ * N_, 256>>>(oa, attn);
    // K3: out = attn @ v.
    av_kernel<<<dim3(DV_ / 128, N_ / 128, B_), 256>>>(attn, v, out);
}

// round 3
// speedup vs baseline: 1.9398x; 1.9398x over previous
#include <cuda_runtime.h>
#include <cuda_bf16.h>
#include <cstdint>

#define B_  8
#define N_  4096
#define M_  2048
#define D_  256
#define DV_ 256
#define INV_T (1.0f / 16.0f)
#define MASK_FILL -1e9f

// ---------------------------------------------------------------------------
// Scratch (__device__ globals; no dynamic allocation allowed).
// ---------------------------------------------------------------------------
__device__ __nv_bfloat16 g_qh[(size_t)B_ * N_ * D_];
__device__ __nv_bfloat16 g_ql[(size_t)B_ * N_ * D_];
__device__ __nv_bfloat16 g_kh[(size_t)B_ * M_ * D_];
__device__ __nv_bfloat16 g_kl[(size_t)B_ * M_ * D_];
__device__ __nv_bfloat16 g_vth[(size_t)B_ * DV_ * M_];   // V^T [B, DV, M]
__device__ __nv_bfloat16 g_vtl[(size_t)B_ * DV_ * M_];
__device__ __nv_bfloat16 g_ah[(size_t)B_ * N_ * M_];     // attn hi/lo for K3
__device__ __nv_bfloat16 g_al[(size_t)B_ * N_ * M_];

// ---------------------------------------------------------------------------
// Helpers (all plain sm_80+/sm_90 PTX — no sm_103a-gated instructions).
// ---------------------------------------------------------------------------
__device__ __forceinline__ uint32_t smem_u32(const void* p) {
    uint32_t a;
    asm("{ .reg .u64 t; cvta.to.shared.u64 t, %1; cvt.u32.u64 %0, t; }"
        : "=r"(a) : "l"(p));
    return a;
}

__device__ __forceinline__ void cp16(uint32_t dst, const void* src) {
    asm volatile("cp.async.cg.shared.global [%0], [%1], 16;"
                 :: "r"(dst), "l"(src));
}
#define CP_COMMIT() asm volatile("cp.async.commit_group;" ::: "memory")
#define CP_WAIT(n)  asm volatile("cp.async.wait_group %0;" :: "n"(n) : "memory")

#define LDSM_X4(r0, r1, r2, r3, addr)                                         \
    asm volatile("ldmatrix.sync.aligned.m8n8.x4.shared.b16 {%0,%1,%2,%3}, [%4];" \
                 : "=r"(r0), "=r"(r1), "=r"(r2), "=r"(r3) : "r"(addr))

#define MMA16816(d, a, b)                                                     \
    asm volatile("mma.sync.aligned.m16n8k16.row.col.f32.bf16.bf16.f32 "       \
                 "{%0,%1,%2,%3}, {%4,%5,%6,%7}, {%8,%9}, {%0,%1,%2,%3};"      \
                 : "+f"((d)[0]), "+f"((d)[1]), "+f"((d)[2]), "+f"((d)[3])     \
                 : "r"((a)[0]), "r"((a)[1]), "r"((a)[2]), "r"((a)[3]),        \
                   "r"((b)[0]), "r"((b)[1]))

// SW64 swizzle for 64-byte rows (32 bf16): conflict-free ldmatrix phases.
__device__ __forceinline__ uint32_t sw64(uint32_t off) {
    return off ^ ((off >> 3) & 0x30);
}

__device__ __forceinline__ void split2(float x, __nv_bfloat16& h, __nv_bfloat16& l) {
    h = __float2bfloat16(x);
    l = __float2bfloat16(x - __bfloat162float(h));
}

// ---------------------------------------------------------------------------
// Prep kernels: fp32 -> bf16 hi/lo splits (q scaled by 1/T), V transposed.
// ---------------------------------------------------------------------------
__global__ void __launch_bounds__(256) prep_q_kernel(const float* __restrict__ q) {
    size_t i = ((size_t)blockIdx.x * 256 + threadIdx.x) * 4;
    float4 x = *(const float4*)(q + i);
    __nv_bfloat16 h0,l0,h1,l1,h2,l2,h3,l3;
    split2(x.x * INV_T, h0, l0); split2(x.y * INV_T, h1, l1);
    split2(x.z * INV_T, h2, l2); split2(x.w * INV_T, h3, l3);
    __nv_bfloat162* dh = (__nv_bfloat162*)(g_qh + i);
    __nv_bfloat162* dl = (__nv_bfloat162*)(g_ql + i);
    dh[0] = {h0, h1}; dh[1] = {h2, h3};
    dl[0] = {l0, l1}; dl[1] = {l2, l3};
}

__global__ void __launch_bounds__(256) prep_k_kernel(const float* __restrict__ k) {
    size_t i = ((size_t)blockIdx.x * 256 + threadIdx.x) * 4;
    float4 x = *(const float4*)(k + i);
    __nv_bfloat16 h0,l0,h1,l1,h2,l2,h3,l3;
    split2(x.x, h0, l0); split2(x.y, h1, l1);
    split2(x.z, h2, l2); split2(x.w, h3, l3);
    __nv_bfloat162* dh = (__nv_bfloat162*)(g_kh + i);
    __nv_bfloat162* dl = (__nv_bfloat162*)(g_kl + i);
    dh[0] = {h0, h1}; dh[1] = {h2, h3};
    dl[0] = {l0, l1}; dl[1] = {l2, l3};
}

__global__ void prep_vt_kernel(const float* __restrict__ v) {
    __shared__ float t[32][33];
    const int b = blockIdx.z, m0 = blockIdx.x * 32, c0 = blockIdx.y * 32;
    for (int j = threadIdx.y; j < 32; j += 8)
        t[j][threadIdx.x] = v[((size_t)b * M_ + m0 + j) * DV_ + c0 + threadIdx.x];
    __syncthreads();
    for (int j = threadIdx.y; j < 32; j += 8) {
        float x = t[threadIdx.x][j];             // v[m0+tx][c0+j]
        __nv_bfloat16 h, l; split2(x, h, l);
        size_t o = ((size_t)b * DV_ + c0 + j) * M_ + m0 + threadIdx.x;
        g_vth[o] = h; g_vtl[o] = l;
    }
}

// ---------------------------------------------------------------------------
// K1: logits = mask ? (q/T)@k^T : -1e9, via mma.sync bf16x3.
// Block tile 128x128, K-chunks of 32, 8 warps (2x4), warp tile 64x32.
// SMEM stage = {Ah,Al,Bh,Bl} x 8KB = 32KB; double buffered via cp.async.
// ---------------------------------------------------------------------------
#define STAGE_BYTES 32768
#define GEMM_SMEM   (2 * STAGE_BYTES)

__global__ void __launch_bounds__(256) qk_mma_kernel(
    const int* __restrict__ mask, float* __restrict__ attn)
{
    extern __shared__ char smem[];
    const uint32_t sb = smem_u32(smem);
    const int tid = threadIdx.x, warp = tid >> 5, lane = tid & 31;
    const int b = blockIdx.z, m0 = blockIdx.x * 128, n0 = blockIdx.y * 128;
    const int wrow = warp >> 2, wcol = warp & 3;

    const __nv_bfloat16* srcs[4] = {
        g_qh + ((size_t)b * N_ + n0) * D_,
        g_ql + ((size_t)b * N_ + n0) * D_,
        g_kh + ((size_t)b * M_ + m0) * D_,
        g_kl + ((size_t)b * M_ + m0) * D_ };

    float acc[4][4][4];
#pragma unroll
    for (int i = 0; i < 4; i++)
#pragma unroll
        for (int j = 0; j < 4; j++)
#pragma unroll
            for (int r = 0; r < 4; r++) acc[i][j][r] = 0.f;

    auto load_stage = [&](int c) {
        const uint32_t stg = sb + (uint32_t)(c & 1) * STAGE_BYTES;
        const int kt = c * 32;
#pragma unroll
        for (int u0 = 0; u0 < 2048; u0 += 256) {
            const int u = u0 + tid;
            const int ti = u >> 9, w = u & 511, r = w >> 2, seg = w & 3;
            cp16(stg + (uint32_t)ti * 8192 + sw64((uint32_t)(r * 64 + seg * 16)),
                 srcs[ti] + (size_t)r * D_ + kt + seg * 8);
        }
        CP_COMMIT();
    };

    load_stage(0);
    const int NC = D_ / 32;                     // 8 chunks
    for (int c = 0; c < NC; c++) {
        if (c + 1 < NC) { load_stage(c + 1); CP_WAIT(1); }
        else           { CP_WAIT(0); }
        __syncthreads();

        const uint32_t stg = sb + (uint32_t)(c & 1) * STAGE_BYTES;
#pragma unroll
        for (int p = 0; p < 3; p++) {
            const uint32_t Abase = stg + (p == 2 ? 8192u : 0u);
            const uint32_t Bbase = stg + 16384u + (p == 1 ? 8192u : 0u);
#pragma unroll
            for (int kk = 0; kk < 2; kk++) {
                uint32_t a[4][4];
#pragma unroll
                for (int i = 0; i < 4; i++) {
                    uint32_t off = (uint32_t)((wrow * 64 + i * 16 + (lane & 15)) * 64
                                              + ((lane >> 4) * 16) + kk * 32);
                    LDSM_X4(a[i][0], a[i][1], a[i][2], a[i][3], Abase + sw64(off));
                }
                uint32_t bf[4][2];
#pragma unroll
                for (int jj = 0; jj < 2; jj++) {
                    uint32_t off = (uint32_t)((wcol * 32 + jj * 16 + (lane & 15)) * 64
                                              + ((lane >> 4) * 16) + kk * 32);
                    uint32_t r0, r1, r2, r3;
                    LDSM_X4(r0, r1, r2, r3, Bbase + sw64(off));
                    bf[jj * 2][0] = r0; bf[jj * 2][1] = r2;
                    bf[jj * 2 + 1][0] = r1; bf[jj * 2 + 1][1] = r3;
                }
#pragma unroll
                for (int i = 0; i < 4; i++)
#pragma unroll
                    for (int j = 0; j < 4; j++)
                        MMA16816(acc[i][j], a[i], bf[j]);
            }
        }
        __syncthreads();
    }

    // Epilogue: mask-select and store fp32 logits.
    const int r_lane = lane >> 2, c_lane = (lane & 3) * 2;
#pragma unroll
    for (int i = 0; i < 4; i++) {
#pragma unroll
        for (int j = 0; j < 4; j++) {
            const int row0 = n0 + wrow * 64 + i * 16 + r_lane;
            const int col  = m0 + wcol * 32 + j * 8 + c_lane;
            const size_t idx0 = ((size_t)b * N_ + row0) * M_ + col;
            const size_t idx1 = idx0 + (size_t)8 * M_;
            int2 mk0 = *(const int2*)(mask + idx0);
            int2 mk1 = *(const int2*)(mask + idx1);
            float2 v0, v1;
            v0.x = mk0.x ? acc[i][j][0] : MASK_FILL;
            v0.y = mk0.y ? acc[i][j][1] : MASK_FILL;
            v1.x = mk1.x ? acc[i][j][2] : MASK_FILL;
            v1.y = mk1.y ? acc[i][j][3] : MASK_FILL;
            *(float2*)(attn + idx0) = v0;
            *(float2*)(attn + idx1) = v1;
        }
    }
}

// ---------------------------------------------------------------------------
// K2: attn = softmax(logits) + softmax(oa) in place; also emit bf16 hi/lo.
// ---------------------------------------------------------------------------
__global__ void __launch_bounds__(256) softmax_add_kernel(
    const float* __restrict__ oa, float* __restrict__ attn)
{
    const size_t row = blockIdx.x;
    float*       s = attn + row * M_;
    const float* o = oa   + row * M_;

    const int tid  = threadIdx.x;
    const int lane = tid & 31;
    const int warp = tid >> 5;
    const int base = tid * 8;

    float sv[8], ov[8];
    float4 s0 = ((const float4*)(s + base))[0], s1 = ((const float4*)(s + base))[1];
    float4 o0 = ((const float4*)(o + base))[0], o1 = ((const float4*)(o + base))[1];
    sv[0]=s0.x; sv[1]=s0.y; sv[2]=s0.z; sv[3]=s0.w;
    sv[4]=s1.x; sv[5]=s1.y; sv[6]=s1.z; sv[7]=s1.w;
    ov[0]=o0.x; ov[1]=o0.y; ov[2]=o0.z; ov[3]=o0.w;
    ov[4]=o1.x; ov[5]=o1.y; ov[6]=o1.z; ov[7]=o1.w;

    float smax = -3.4e38f, omax = -3.4e38f;
#pragma unroll
    for (int i = 0; i < 8; i++) { smax = fmaxf(smax, sv[i]); omax = fmaxf(omax, ov[i]); }
#pragma unroll
    for (int off = 16; off > 0; off >>= 1) {
        smax = fmaxf(smax, __shfl_xor_sync(0xffffffffu, smax, off));
        omax = fmaxf(omax, __shfl_xor_sync(0xffffffffu, omax, off));
    }
    __shared__ float red[4][8];
    if (lane == 0) { red[0][warp] = smax; red[1][warp] = omax; }
    __syncthreads();
#pragma unroll
    for (int w = 0; w < 8; w++) { smax = fmaxf(smax, red[0][w]); omax = fmaxf(omax, red[1][w]); }

    float ssum = 0.f, osum = 0.f;
#pragma unroll
    for (int i = 0; i < 8; i++) {
        sv[i] = __expf(sv[i] - smax);
        ov[i] = __expf(ov[i] - omax);
        ssum += sv[i]; osum += ov[i];
    }
#pragma unroll
    for (int off = 16; off > 0; off >>= 1) {
        ssum += __shfl_xor_sync(0xffffffffu, ssum, off);
        osum += __shfl_xor_sync(0xffffffffu, osum, off);
    }
    if (lane == 0) { red[2][warp] = ssum; red[3][warp] = osum; }
    __syncthreads();
    ssum = 0.f; osum = 0.f;
#pragma unroll
    for (int w = 0; w < 8; w++) { ssum += red[2][w]; osum += red[3][w]; }
    const float sinv = 1.0f / ssum;
    const float oinv = 1.0f / osum;

    float vals[8];
    __nv_bfloat16 h[8], l[8];
#pragma unroll
    for (int i = 0; i < 8; i++) {
        vals[i] = sv[i] * sinv + ov[i] * oinv;
        split2(vals[i], h[i], l[i]);
    }
    ((float4*)(s + base))[0] = make_float4(vals[0], vals[1], vals[2], vals[3]);
    ((float4*)(s + base))[1] = make_float4(vals[4], vals[5], vals[6], vals[7]);
    __nv_bfloat162* dh = (__nv_bfloat162*)(g_ah + row * M_ + base);
    __nv_bfloat162* dl = (__nv_bfloat162*)(g_al + row * M_ + base);
    dh[0] = {h[0], h[1]}; dh[1] = {h[2], h[3]}; dh[2] = {h[4], h[5]}; dh[3] = {h[6], h[7]};
    dl[0] = {l[0], l[1]}; dl[1] = {l[2], l[3]}; dl[2] = {l[4], l[5]}; dl[3] = {l[6], l[7]};
}

// ---------------------------------------------------------------------------
// K3: out = attn @ v via mma.sync bf16x3. Same structure; K = M_ = 2048.
// A = attn splits [N_, M_], B = V^T splits [DV_, M_].
// ---------------------------------------------------------------------------
__global__ void __launch_bounds__(256) av_mma_kernel(float* __restrict__ out)
{
    extern __shared__ char smem[];
    const uint32_t sb = smem_u32(smem);
    const int tid = threadIdx.x, warp = tid >> 5, lane = tid & 31;
    const int b = blockIdx.z, c0 = blockIdx.x * 128, n0 = blockIdx.y * 128;
    const int wrow = warp >> 2, wcol = warp & 3;

    const __nv_bfloat16* srcs[4] = {
        g_ah  + ((size_t)b * N_  + n0) * M_,
        g_al  + ((size_t)b * N_  + n0) * M_,
        g_vth + ((size_t)b * DV_ + c0) * M_,
        g_vtl + ((size_t)b * DV_ + c0) * M_ };

    float acc[4][4][4];
#pragma unroll
    for (int i = 0; i < 4; i++)
#pragma unroll
        for (int j = 0; j < 4; j++)
#pragma unroll
            for (int r = 0; r < 4; r++) acc[i][j][r] = 0.f;

    auto load_stage = [&](int c) {
        const uint32_t stg = sb + (uint32_t)(c & 1) * STAGE_BYTES;
        const int kt = c * 32;
#pragma unroll
        for (int u0 = 0; u0 < 2048; u0 += 256) {
            const int u = u0 + tid;
            const int ti = u >> 9, w = u & 511, r = w >> 2, seg = w & 3;
            cp16(stg + (uint32_t)ti * 8192 + sw64((uint32_t)(r * 64 + seg * 16)),
                 srcs[ti] + (size_t)r * M_ + kt + seg * 8);
        }
        CP_COMMIT();
    };

    load_stage(0);
    const int NC = M_ / 32;                     // 64 chunks
    for (int c = 0; c < NC; c++) {
        if (c + 1 < NC) { load_stage(c + 1); CP_WAIT(1); }
        else           { CP_WAIT(0); }
        __syncthreads();

        const uint32_t stg = sb + (uint32_t)(c & 1) * STAGE_BYTES;
#pragma unroll
        for (int p = 0; p < 3; p++) {
            const uint32_t Abase = stg + (p == 2 ? 8192u : 0u);
            const uint32_t Bbase = stg + 16384u + (p == 1 ? 8192u : 0u);
#pragma unroll
            for (int kk = 0; kk < 2; kk++) {
                uint32_t a[4][4];
#pragma unroll
                for (int i = 0; i < 4; i++) {
                    uint32_t off = (uint32_t)((wrow * 64 + i * 16 + (lane & 15)) * 64
                                              + ((lane >> 4) * 16) + kk * 32);
                    LDSM_X4(a[i][0], a[i][1], a[i][2], a[i][3], Abase + sw64(off));
                }
                uint32_t bf[4][2];
#pragma unroll
                for (int jj = 0; jj < 2; jj++) {
                    uint32_t off = (uint32_t)((wcol * 32 + jj * 16 + (lane & 15)) * 64
                                              + ((lane >> 4) * 16) + kk * 32);
                    uint32_t r0, r1, r2, r3;
                    LDSM_X4(r0, r1, r2, r3, Bbase + sw64(off));
                    bf[jj * 2][0] = r0; bf[jj * 2][1] = r2;
                    bf[jj * 2 + 1][0] = r1; bf[jj * 2 + 1][1] = r3;
                }
#pragma unroll
                for (int i = 0; i < 4; i++)
#pragma unroll
                    for (int j = 0; j < 4; j++)
                        MMA16816(acc[i][j], a[i], bf[j]);
            }
        }
        __syncthreads();
    }

    const int r_lane = lane >> 2, c_lane = (lane & 3) * 2;
#pragma unroll
    for (int i = 0; i < 4; i++) {
#pragma unroll
        for (int j = 0; j < 4; j++) {
            const int row0 = n0 + wrow * 64 + i * 16 + r_lane;
            const int col  = c0 + wcol * 32 + j * 8 + c_lane;
            const size_t idx0 = ((size_t)b * N_ + row0) * DV_ + col;
            const size_t idx1 = idx0 + (size_t)8 * DV_;
            *(float2*)(out + idx0) = make_float2(acc[i][j][0], acc[i][j][1]);
            *(float2*)(out + idx1) = make_float2(acc[i][j][2], acc[i][j][3]);
        }
    }
}

// ---------------------------------------------------------------------------
extern "C" void kernel_launch(void* const* d_in, const int* in_sizes, int n_in,
                              void* d_out, int out_size)
{
    const float* q    = (const float*)d_in[0];
    const float* k    = (const float*)d_in[1];
    const float* v    = (const float*)d_in[2];
    const float* oa   = (const float*)d_in[3];
    const int*   mask = (const int*)d_in[4];
    // d_in[5] = feature; always truthy for these shapes, ignored.

    float* out  = (float*)d_out;                        // [B, N, DV]
    float* attn = out + (size_t)B_ * N_ * DV_;          // [B, N, M]

    cudaFuncSetAttribute(qk_mma_kernel, cudaFuncAttributeMaxDynamicSharedMemorySize, GEMM_SMEM);
    cudaFuncSetAttribute(av_mma_kernel, cudaFuncAttributeMaxDynamicSharedMemorySize, GEMM_SMEM);

    prep_q_kernel<<<(size_t)B_ * N_ * D_ / 4 / 256, 256>>>(q);
    prep_k_kernel<<<(size_t)B_ * M_ * D_ / 4 / 256, 256>>>(k);
    prep_vt_kernel<<<dim3(M_ / 32, DV_ / 32, B_), dim3(32, 8)>>>(v);

    qk_mma_kernel<<<dim3(M_ / 128, N_ / 128, B_), 256, GEMM_SMEM>>>(mask, attn);
    softmax_add_kernel<<<B_ * N_, 256>>>(oa, attn);
    av_mma_kernel<<<dim3(DV_ / 128, N_ / 128, B_), 256, GEMM_SMEM>>>(out);
}

// round 4
// speedup vs baseline: 1.9801x; 1.0208x over previous
#include <cuda_runtime.h>
#include <cuda_bf16.h>
#include <cstdint>

#define B_  8
#define N_  4096
#define M_  2048
#define D_  256
#define DV_ 256
#define INV_T (1.0f / 16.0f)
#define MASK_FILL -1e9f

// ---------------------------------------------------------------------------
// Scratch (__device__ globals; no dynamic allocation allowed).
// ---------------------------------------------------------------------------
__device__ __nv_bfloat16 g_qh[(size_t)B_ * N_ * D_];
__device__ __nv_bfloat16 g_ql[(size_t)B_ * N_ * D_];
__device__ __nv_bfloat16 g_kh[(size_t)B_ * M_ * D_];
__device__ __nv_bfloat16 g_kl[(size_t)B_ * M_ * D_];
__device__ __nv_bfloat16 g_vth[(size_t)B_ * DV_ * M_];   // V^T [B, DV, M]
__device__ __nv_bfloat16 g_vtl[(size_t)B_ * DV_ * M_];
__device__ __nv_bfloat16 g_ah[(size_t)B_ * N_ * M_];     // attn hi/lo for K3
__device__ __nv_bfloat16 g_al[(size_t)B_ * N_ * M_];

// ---------------------------------------------------------------------------
// Helpers (plain sm_80+ PTX only — tcgen05 is feature-gated off this target).
// ---------------------------------------------------------------------------
__device__ __forceinline__ uint32_t smem_u32(const void* p) {
    uint32_t a;
    asm("{ .reg .u64 t; cvta.to.shared.u64 t, %1; cvt.u32.u64 %0, t; }"
        : "=r"(a) : "l"(p));
    return a;
}

__device__ __forceinline__ void cp16(uint32_t dst, const void* src) {
    asm volatile("cp.async.cg.shared.global [%0], [%1], 16;"
                 :: "r"(dst), "l"(src));
}
#define CP_COMMIT() asm volatile("cp.async.commit_group;" ::: "memory")
#define CP_WAIT(n)  asm volatile("cp.async.wait_group %0;" :: "n"(n) : "memory")

#define LDSM_X4(r0, r1, r2, r3, addr)                                         \
    asm volatile("ldmatrix.sync.aligned.m8n8.x4.shared.b16 {%0,%1,%2,%3}, [%4];" \
                 : "=r"(r0), "=r"(r1), "=r"(r2), "=r"(r3) : "r"(addr))

#define MMA16816(d, a, b)                                                     \
    asm volatile("mma.sync.aligned.m16n8k16.row.col.f32.bf16.bf16.f32 "       \
                 "{%0,%1,%2,%3}, {%4,%5,%6,%7}, {%8,%9}, {%0,%1,%2,%3};"      \
                 : "+f"((d)[0]), "+f"((d)[1]), "+f"((d)[2]), "+f"((d)[3])     \
                 : "r"((a)[0]), "r"((a)[1]), "r"((a)[2]), "r"((a)[3]),        \
                   "r"((b)[0]), "r"((b)[1]))

// SW64 swizzle for 64-byte rows (32 bf16): conflict-free ldmatrix phases.
__device__ __forceinline__ uint32_t sw64(uint32_t off) {
    return off ^ ((off >> 3) & 0x30);
}

__device__ __forceinline__ void split2(float x, __nv_bfloat16& h, __nv_bfloat16& l) {
    h = __float2bfloat16(x);
    l = __float2bfloat16(x - __bfloat162float(h));
}

// ---------------------------------------------------------------------------
// Prep kernels: fp32 -> bf16 hi/lo splits (q scaled by 1/T), V transposed.
// ---------------------------------------------------------------------------
__global__ void __launch_bounds__(256) prep_q_kernel(const float* __restrict__ q) {
    size_t i = ((size_t)blockIdx.x * 256 + threadIdx.x) * 4;
    float4 x = *(const float4*)(q + i);
    __nv_bfloat16 h0,l0,h1,l1,h2,l2,h3,l3;
    split2(x.x * INV_T, h0, l0); split2(x.y * INV_T, h1, l1);
    split2(x.z * INV_T, h2, l2); split2(x.w * INV_T, h3, l3);
    __nv_bfloat162* dh = (__nv_bfloat162*)(g_qh + i);
    __nv_bfloat162* dl = (__nv_bfloat162*)(g_ql + i);
    dh[0] = {h0, h1}; dh[1] = {h2, h3};
    dl[0] = {l0, l1}; dl[1] = {l2, l3};
}

__global__ void __launch_bounds__(256) prep_k_kernel(const float* __restrict__ k) {
    size_t i = ((size_t)blockIdx.x * 256 + threadIdx.x) * 4;
    float4 x = *(const float4*)(k + i);
    __nv_bfloat16 h0,l0,h1,l1,h2,l2,h3,l3;
    split2(x.x, h0, l0); split2(x.y, h1, l1);
    split2(x.z, h2, l2); split2(x.w, h3, l3);
    __nv_bfloat162* dh = (__nv_bfloat162*)(g_kh + i);
    __nv_bfloat162* dl = (__nv_bfloat162*)(g_kl + i);
    dh[0] = {h0, h1}; dh[1] = {h2, h3};
    dl[0] = {l0, l1}; dl[1] = {l2, l3};
}

__global__ void prep_vt_kernel(const float* __restrict__ v) {
    __shared__ float t[32][33];
    const int b = blockIdx.z, m0 = blockIdx.x * 32, c0 = blockIdx.y * 32;
    for (int j = threadIdx.y; j < 32; j += 8)
        t[j][threadIdx.x] = v[((size_t)b * M_ + m0 + j) * DV_ + c0 + threadIdx.x];
    __syncthreads();
    for (int j = threadIdx.y; j < 32; j += 8) {
        float x = t[threadIdx.x][j];             // v[m0+tx][c0+j]
        __nv_bfloat16 h, l; split2(x, h, l);
        size_t o = ((size_t)b * DV_ + c0 + j) * M_ + m0 + threadIdx.x;
        g_vth[o] = h; g_vtl[o] = l;
    }
}

// ---------------------------------------------------------------------------
// GEMM kernels: block 128x128, 512 threads (16 warps, warp tile 32x32),
// K-chunks of 32, 3-stage cp.async ring, bf16x3 error-compensated MMA.
// SMEM stage = {Ah,Al,Bh,Bl} x 8KB = 32KB; 3 stages = 96KB.
// ---------------------------------------------------------------------------
#define STAGE_BYTES 32768
#define GEMM_SMEM   (3 * STAGE_BYTES)

// Shared mainloop body used by both GEMM kernels.
// srcs: {Ah, Al, Bh, Bl} base pointers for this block; sstride: row stride.
// acc[i][j][4]: i in 0..1 (16-row), j in 0..3 (8-col).
template <int NC>
__device__ __forceinline__ void gemm_mainloop(
    const __nv_bfloat16* const srcs[4], const size_t sstride,
    uint32_t sb, int tid, int wrow, int wcol, int lane, float acc[2][4][4])
{
    auto load_stage = [&](int c) {
        const uint32_t stg = sb + (uint32_t)(c % 3) * STAGE_BYTES;
        const int kt = c * 32;
#pragma unroll
        for (int u0 = 0; u0 < 2048; u0 += 512) {
            const int u = u0 + tid;
            const int ti = u >> 9, w = u & 511, r = w >> 2, seg = w & 3;
            cp16(stg + (uint32_t)ti * 8192 + sw64((uint32_t)(r * 64 + seg * 16)),
                 srcs[ti] + (size_t)r * sstride + kt + seg * 8);
        }
        CP_COMMIT();
    };

    load_stage(0);
    load_stage(1);

    for (int c = 0; c < NC; c++) {
        __syncthreads();                 // all warps done with stage (c-1)%3
        if (c + 2 < NC) { load_stage(c + 2); CP_WAIT(2); }
        else if (c + 1 < NC) { CP_WAIT(1); }
        else { CP_WAIT(0); }
        __syncthreads();                 // stage c visible to all warps

        const uint32_t stg = sb + (uint32_t)(c % 3) * STAGE_BYTES;
#pragma unroll
        for (int kk = 0; kk < 2; kk++) {
            uint32_t ah[2][4], al[2][4], bh[4][2], bl[4][2];
#pragma unroll
            for (int i = 0; i < 2; i++) {
                uint32_t off = (uint32_t)((wrow * 32 + i * 16 + (lane & 15)) * 64
                                          + ((lane >> 4) * 16) + kk * 32);
                LDSM_X4(ah[i][0], ah[i][1], ah[i][2], ah[i][3], stg + sw64(off));
                LDSM_X4(al[i][0], al[i][1], al[i][2], al[i][3], stg + 8192u + sw64(off));
            }
#pragma unroll
            for (int jj = 0; jj < 2; jj++) {
                uint32_t off = (uint32_t)((wcol * 32 + jj * 16 + (lane & 15)) * 64
                                          + ((lane >> 4) * 16) + kk * 32);
                uint32_t r0, r1, r2, r3;
                LDSM_X4(r0, r1, r2, r3, stg + 16384u + sw64(off));
                bh[jj * 2][0] = r0; bh[jj * 2][1] = r2;
                bh[jj * 2 + 1][0] = r1; bh[jj * 2 + 1][1] = r3;
                LDSM_X4(r0, r1, r2, r3, stg + 24576u + sw64(off));
                bl[jj * 2][0] = r0; bl[jj * 2][1] = r2;
                bl[jj * 2 + 1][0] = r1; bl[jj * 2 + 1][1] = r3;
            }
#pragma unroll
            for (int i = 0; i < 2; i++)
#pragma unroll
                for (int j = 0; j < 4; j++) {
                    MMA16816(acc[i][j], ah[i], bh[j]);   // hi*hi
                    MMA16816(acc[i][j], ah[i], bl[j]);   // hi*lo
                    MMA16816(acc[i][j], al[i], bh[j]);   // lo*hi
                }
        }
    }
}

// K1: logits = mask ? (q/T)@k^T : -1e9.
__global__ void __launch_bounds__(512) qk_mma_kernel(
    const int* __restrict__ mask, float* __restrict__ attn)
{
    extern __shared__ char smem[];
    const uint32_t sb = smem_u32(smem);
    const int tid = threadIdx.x, warp = tid >> 5, lane = tid & 31;
    const int b = blockIdx.z, m0 = blockIdx.x * 128, n0 = blockIdx.y * 128;
    const int wrow = warp >> 2, wcol = warp & 3;

    const __nv_bfloat16* srcs[4] = {
        g_qh + ((size_t)b * N_ + n0) * D_,
        g_ql + ((size_t)b * N_ + n0) * D_,
        g_kh + ((size_t)b * M_ + m0) * D_,
        g_kl + ((size_t)b * M_ + m0) * D_ };

    float acc[2][4][4];
#pragma unroll
    for (int i = 0; i < 2; i++)
#pragma unroll
        for (int j = 0; j < 4; j++)
#pragma unroll
            for (int r = 0; r < 4; r++) acc[i][j][r] = 0.f;

    gemm_mainloop<D_ / 32>(srcs, D_, sb, tid, wrow, wcol, lane, acc);

    const int r_lane = lane >> 2, c_lane = (lane & 3) * 2;
#pragma unroll
    for (int i = 0; i < 2; i++) {
#pragma unroll
        for (int j = 0; j < 4; j++) {
            const int row0 = n0 + wrow * 32 + i * 16 + r_lane;
            const int col  = m0 + wcol * 32 + j * 8 + c_lane;
            const size_t idx0 = ((size_t)b * N_ + row0) * M_ + col;
            const size_t idx1 = idx0 + (size_t)8 * M_;
            int2 mk0 = *(const int2*)(mask + idx0);
            int2 mk1 = *(const int2*)(mask + idx1);
            float2 v0, v1;
            v0.x = mk0.x ? acc[i][j][0] : MASK_FILL;
            v0.y = mk0.y ? acc[i][j][1] : MASK_FILL;
            v1.x = mk1.x ? acc[i][j][2] : MASK_FILL;
            v1.y = mk1.y ? acc[i][j][3] : MASK_FILL;
            *(float2*)(attn + idx0) = v0;
            *(float2*)(attn + idx1) = v1;
        }
    }
}

// K3: out = attn @ v. A = attn splits [N_, M_], B = V^T splits [DV_, M_].
__global__ void __launch_bounds__(512) av_mma_kernel(float* __restrict__ out)
{
    extern __shared__ char smem[];
    const uint32_t sb = smem_u32(smem);
    const int tid = threadIdx.x, warp = tid >> 5, lane = tid & 31;
    const int b = blockIdx.z, c0 = blockIdx.x * 128, n0 = blockIdx.y * 128;
    const int wrow = warp >> 2, wcol = warp & 3;

    const __nv_bfloat16* srcs[4] = {
        g_ah  + ((size_t)b * N_  + n0) * M_,
        g_al  + ((size_t)b * N_  + n0) * M_,
        g_vth + ((size_t)b * DV_ + c0) * M_,
        g_vtl + ((size_t)b * DV_ + c0) * M_ };

    float acc[2][4][4];
#pragma unroll
    for (int i = 0; i < 2; i++)
#pragma unroll
        for (int j = 0; j < 4; j++)
#pragma unroll
            for (int r = 0; r < 4; r++) acc[i][j][r] = 0.f;

    gemm_mainloop<M_ / 32>(srcs, M_, sb, tid, wrow, wcol, lane, acc);

    const int r_lane = lane >> 2, c_lane = (lane & 3) * 2;
#pragma unroll
    for (int i = 0; i < 2; i++) {
#pragma unroll
        for (int j = 0; j < 4; j++) {
            const int row0 = n0 + wrow * 32 + i * 16 + r_lane;
            const int col  = c0 + wcol * 32 + j * 8 + c_lane;
            const size_t idx0 = ((size_t)b * N_ + row0) * DV_ + col;
            const size_t idx1 = idx0 + (size_t)8 * DV_;
            *(float2*)(out + idx0) = make_float2(acc[i][j][0], acc[i][j][1]);
            *(float2*)(out + idx1) = make_float2(acc[i][j][2], acc[i][j][3]);
        }
    }
}

// ---------------------------------------------------------------------------
// K2: attn = softmax(logits) + softmax(oa) in place; also emit bf16 hi/lo.
// ---------------------------------------------------------------------------
__global__ void __launch_bounds__(256) softmax_add_kernel(
    const float* __restrict__ oa, float* __restrict__ attn)
{
    const size_t row = blockIdx.x;
    float*       s = attn + row * M_;
    const float* o = oa   + row * M_;

    const int tid  = threadIdx.x;
    const int lane = tid & 31;
    const int warp = tid >> 5;
    const int base = tid * 8;

    float sv[8], ov[8];
    float4 s0 = ((const float4*)(s + base))[0], s1 = ((const float4*)(s + base))[1];
    float4 o0 = ((const float4*)(o + base))[0], o1 = ((const float4*)(o + base))[1];
    sv[0]=s0.x; sv[1]=s0.y; sv[2]=s0.z; sv[3]=s0.w;
    sv[4]=s1.x; sv[5]=s1.y; sv[6]=s1.z; sv[7]=s1.w;
    ov[0]=o0.x; ov[1]=o0.y; ov[2]=o0.z; ov[3]=o0.w;
    ov[4]=o1.x; ov[5]=o1.y; ov[6]=o1.z; ov[7]=o1.w;

    float smax = -3.4e38f, omax = -3.4e38f;
#pragma unroll
    for (int i = 0; i < 8; i++) { smax = fmaxf(smax, sv[i]); omax = fmaxf(omax, ov[i]); }
#pragma unroll
    for (int off = 16; off > 0; off >>= 1) {
        smax = fmaxf(smax, __shfl_xor_sync(0xffffffffu, smax, off));
        omax = fmaxf(omax, __shfl_xor_sync(0xffffffffu, omax, off));
    }
    __shared__ float red[4][8];
    if (lane == 0) { red[0][warp] = smax; red[1][warp] = omax; }
    __syncthreads();
#pragma unroll
    for (int w = 0; w < 8; w++) { smax = fmaxf(smax, red[0][w]); omax = fmaxf(omax, red[1][w]); }

    float ssum = 0.f, osum = 0.f;
#pragma unroll
    for (int i = 0; i < 8; i++) {
        sv[i] = __expf(sv[i] - smax);
        ov[i] = __expf(ov[i] - omax);
        ssum += sv[i]; osum += ov[i];
    }
#pragma unroll
    for (int off = 16; off > 0; off >>= 1) {
        ssum += __shfl_xor_sync(0xffffffffu, ssum, off);
        osum += __shfl_xor_sync(0xffffffffu, osum, off);
    }
    if (lane == 0) { red[2][warp] = ssum; red[3][warp] = osum; }
    __syncthreads();
    ssum = 0.f; osum = 0.f;
#pragma unroll
    for (int w = 0; w < 8; w++) { ssum += red[2][w]; osum += red[3][w]; }
    const float sinv = 1.0f / ssum;
    const float oinv = 1.0f / osum;

    float vals[8];
    __nv_bfloat16 h[8], l[8];
#pragma unroll
    for (int i = 0; i < 8; i++) {
        vals[i] = sv[i] * sinv + ov[i] * oinv;
        split2(vals[i], h[i], l[i]);
    }
    ((float4*)(s + base))[0] = make_float4(vals[0], vals[1], vals[2], vals[3]);
    ((float4*)(s + base))[1] = make_float4(vals[4], vals[5], vals[6], vals[7]);
    __nv_bfloat162* dh = (__nv_bfloat162*)(g_ah + row * M_ + base);
    __nv_bfloat162* dl = (__nv_bfloat162*)(g_al + row * M_ + base);
    dh[0] = {h[0], h[1]}; dh[1] = {h[2], h[3]}; dh[2] = {h[4], h[5]}; dh[3] = {h[6], h[7]};
    dl[0] = {l[0], l[1]}; dl[1] = {l[2], l[3]}; dl[2] = {l[4], l[5]}; dl[3] = {l[6], l[7]};
}

// ---------------------------------------------------------------------------
extern "C" void kernel_launch(void* const* d_in, const int* in_sizes, int n_in,
                              void* d_out, int out_size)
{
    const float* q    = (const float*)d_in[0];
    const float* k    = (const float*)d_in[1];
    const float* v    = (const float*)d_in[2];
    const float* oa   = (const float*)d_in[3];
    const int*   mask = (const int*)d_in[4];
    // d_in[5] = feature; always truthy for these shapes, ignored.

    float* out  = (float*)d_out;                        // [B, N, DV]
    float* attn = out + (size_t)B_ * N_ * DV_;          // [B, N, M]

    cudaFuncSetAttribute(qk_mma_kernel, cudaFuncAttributeMaxDynamicSharedMemorySize, GEMM_SMEM);
    cudaFuncSetAttribute(av_mma_kernel, cudaFuncAttributeMaxDynamicSharedMemorySize, GEMM_SMEM);

    prep_q_kernel<<<(size_t)B_ * N_ * D_ / 4 / 256, 256>>>(q);
    prep_k_kernel<<<(size_t)B_ * M_ * D_ / 4 / 256, 256>>>(k);
    prep_vt_kernel<<<dim3(M_ / 32, DV_ / 32, B_), dim3(32, 8)>>>(v);

    qk_mma_kernel<<<dim3(M_ / 128, N_ / 128, B_), 512, GEMM_SMEM>>>(mask, attn);
    softmax_add_kernel<<<B_ * N_, 256>>>(oa, attn);
    av_mma_kernel<<<dim3(DV_ / 128, N_ / 128, B_), 512, GEMM_SMEM>>>(out);
}

// round 5
// speedup vs baseline: 2.6732x; 1.3500x over previous
#include <cuda_runtime.h>
#include <cuda_fp16.h>
#include <cstdint>

#define B_  8
#define N_  4096
#define M_  2048
#define D_  256
#define DV_ 256
#define INV_T (1.0f / 16.0f)
#define MASK_FILL -1e9f

// ---------------------------------------------------------------------------
// Scratch (__device__ globals; no dynamic allocation allowed).
// fp16 2-term scheme: A operand split hi/lo (22-bit), B operand single fp16.
// ---------------------------------------------------------------------------
__device__ __half g_qh[(size_t)B_ * N_ * D_];
__device__ __half g_ql[(size_t)B_ * N_ * D_];
__device__ __half g_k16[(size_t)B_ * M_ * D_];
__device__ __half g_vt16[(size_t)B_ * DV_ * M_];   // V^T [B, DV, M]
__device__ __half g_ah[(size_t)B_ * N_ * M_];      // attn hi/lo for K3
__device__ __half g_al[(size_t)B_ * N_ * M_];

// ---------------------------------------------------------------------------
// Helpers (plain sm_80+ PTX only — tcgen05 is feature-gated off this target).
// ---------------------------------------------------------------------------
__device__ __forceinline__ uint32_t smem_u32(const void* p) {
    uint32_t a;
    asm("{ .reg .u64 t; cvta.to.shared.u64 t, %1; cvt.u32.u64 %0, t; }"
        : "=r"(a) : "l"(p));
    return a;
}

__device__ __forceinline__ void cp16(uint32_t dst, const void* src) {
    asm volatile("cp.async.cg.shared.global [%0], [%1], 16;"
                 :: "r"(dst), "l"(src));
}
#define CP_COMMIT() asm volatile("cp.async.commit_group;" ::: "memory")
#define CP_WAIT(n)  asm volatile("cp.async.wait_group %0;" :: "n"(n) : "memory")

#define LDSM_X4(r0, r1, r2, r3, addr)                                         \
    asm volatile("ldmatrix.sync.aligned.m8n8.x4.shared.b16 {%0,%1,%2,%3}, [%4];" \
                 : "=r"(r0), "=r"(r1), "=r"(r2), "=r"(r3) : "r"(addr))

#define MMA16816(d, a, b)                                                     \
    asm volatile("mma.sync.aligned.m16n8k16.row.col.f32.f16.f16.f32 "         \
                 "{%0,%1,%2,%3}, {%4,%5,%6,%7}, {%8,%9}, {%0,%1,%2,%3};"      \
                 : "+f"((d)[0]), "+f"((d)[1]), "+f"((d)[2]), "+f"((d)[3])     \
                 : "r"((a)[0]), "r"((a)[1]), "r"((a)[2]), "r"((a)[3]),        \
                   "r"((b)[0]), "r"((b)[1]))

// SW64 swizzle for 64-byte rows (32 fp16): conflict-free ldmatrix phases.
__device__ __forceinline__ uint32_t sw64(uint32_t off) {
    return off ^ ((off >> 3) & 0x30);
}

__device__ __forceinline__ void split2h(float x, __half& h, __half& l) {
    h = __float2half(x);
    l = __float2half(x - __half2float(h));
}

// ---------------------------------------------------------------------------
// Prep kernels.
// ---------------------------------------------------------------------------
__global__ void __launch_bounds__(256) prep_q_kernel(const float* __restrict__ q) {
    size_t i = ((size_t)blockIdx.x * 256 + threadIdx.x) * 4;
    float4 x = *(const float4*)(q + i);
    __half h0,l0,h1,l1,h2,l2,h3,l3;
    split2h(x.x * INV_T, h0, l0); split2h(x.y * INV_T, h1, l1);
    split2h(x.z * INV_T, h2, l2); split2h(x.w * INV_T, h3, l3);
    __half2* dh = (__half2*)(g_qh + i);
    __half2* dl = (__half2*)(g_ql + i);
    dh[0] = {h0, h1}; dh[1] = {h2, h3};
    dl[0] = {l0, l1}; dl[1] = {l2, l3};
}

__global__ void __launch_bounds__(256) prep_k_kernel(const float* __restrict__ k) {
    size_t i = ((size_t)blockIdx.x * 256 + threadIdx.x) * 4;
    float4 x = *(const float4*)(k + i);
    __half2* d = (__half2*)(g_k16 + i);
    d[0] = {__float2half(x.x), __float2half(x.y)};
    d[1] = {__float2half(x.z), __float2half(x.w)};
}

__global__ void prep_vt_kernel(const float* __restrict__ v) {
    __shared__ float t[32][33];
    const int b = blockIdx.z, m0 = blockIdx.x * 32, c0 = blockIdx.y * 32;
    for (int j = threadIdx.y; j < 32; j += 8)
        t[j][threadIdx.x] = v[((size_t)b * M_ + m0 + j) * DV_ + c0 + threadIdx.x];
    __syncthreads();
    for (int j = threadIdx.y; j < 32; j += 8) {
        size_t o = ((size_t)b * DV_ + c0 + j) * M_ + m0 + threadIdx.x;
        g_vt16[o] = __float2half(t[threadIdx.x][j]);
    }
}

// ---------------------------------------------------------------------------
// GEMM mainloop: block 128x128, 512 threads (16 warps, warp tile 32x32),
// K-chunks of 32, 4-stage cp.async ring, fp16 2-term compensated MMA.
// Stage = {Ah, Al, B} x 8KB = 24KB; 4 stages = 96KB.
// ---------------------------------------------------------------------------
#define STAGE_BYTES 24576
#define GEMM_SMEM   (4 * STAGE_BYTES)

template <int NC>
__device__ __forceinline__ void gemm_mainloop(
    const __half* const srcs[3], const size_t sstride,
    uint32_t sb, int tid, int wrow, int wcol, int lane, float acc[2][4][4])
{
    auto load_stage = [&](int c) {
        const uint32_t stg = sb + (uint32_t)(c & 3) * STAGE_BYTES;
        const int kt = c * 32;
#pragma unroll
        for (int u0 = 0; u0 < 1536; u0 += 512) {
            const int u = u0 + tid;
            const int ti = u >> 9, w = u & 511, r = w >> 2, seg = w & 3;
            cp16(stg + (uint32_t)ti * 8192 + sw64((uint32_t)(r * 64 + seg * 16)),
                 srcs[ti] + (size_t)r * sstride + kt + seg * 8);
        }
        CP_COMMIT();
    };

    load_stage(0);
    if (NC > 1) load_stage(1);
    if (NC > 2) load_stage(2);

    for (int c = 0; c < NC; c++) {
        if (c + 3 <= NC) { CP_WAIT(2); }
        else if (c + 2 == NC) { CP_WAIT(1); }
        else { CP_WAIT(0); }
        __syncthreads();                 // stage c visible; all done computing c-1

        const uint32_t stg = sb + (uint32_t)(c & 3) * STAGE_BYTES;
#pragma unroll
        for (int kk = 0; kk < 2; kk++) {
            uint32_t ah[2][4], al[2][4], bf[4][2];
#pragma unroll
            for (int i = 0; i < 2; i++) {
                uint32_t off = (uint32_t)((wrow * 32 + i * 16 + (lane & 15)) * 64
                                          + ((lane >> 4) * 16) + kk * 32);
                LDSM_X4(ah[i][0], ah[i][1], ah[i][2], ah[i][3], stg + sw64(off));
                LDSM_X4(al[i][0], al[i][1], al[i][2], al[i][3], stg + 8192u + sw64(off));
            }
#pragma unroll
            for (int jj = 0; jj < 2; jj++) {
                uint32_t off = (uint32_t)((wcol * 32 + jj * 16 + (lane & 15)) * 64
                                          + ((lane >> 4) * 16) + kk * 32);
                uint32_t r0, r1, r2, r3;
                LDSM_X4(r0, r1, r2, r3, stg + 16384u + sw64(off));
                bf[jj * 2][0] = r0; bf[jj * 2][1] = r2;
                bf[jj * 2 + 1][0] = r1; bf[jj * 2 + 1][1] = r3;
            }
#pragma unroll
            for (int i = 0; i < 2; i++)
#pragma unroll
                for (int j = 0; j < 4; j++) {
                    MMA16816(acc[i][j], ah[i], bf[j]);   // hi * B
                    MMA16816(acc[i][j], al[i], bf[j]);   // lo * B
                }
        }
        if (c + 3 < NC) load_stage(c + 3);
    }
}

// K1: logits = mask ? (q/T)@k^T : -1e9.
__global__ void __launch_bounds__(512) qk_mma_kernel(
    const int* __restrict__ mask, float* __restrict__ attn)
{
    extern __shared__ char smem[];
    const uint32_t sb = smem_u32(smem);
    const int tid = threadIdx.x, warp = tid >> 5, lane = tid & 31;
    const int b = blockIdx.z, m0 = blockIdx.x * 128, n0 = blockIdx.y * 128;
    const int wrow = warp >> 2, wcol = warp & 3;

    const __half* srcs[3] = {
        g_qh  + ((size_t)b * N_ + n0) * D_,
        g_ql  + ((size_t)b * N_ + n0) * D_,
        g_k16 + ((size_t)b * M_ + m0) * D_ };

    float acc[2][4][4];
#pragma unroll
    for (int i = 0; i < 2; i++)
#pragma unroll
        for (int j = 0; j < 4; j++)
#pragma unroll
            for (int r = 0; r < 4; r++) acc[i][j][r] = 0.f;

    gemm_mainloop<D_ / 32>(srcs, D_, sb, tid, wrow, wcol, lane, acc);

    const int r_lane = lane >> 2, c_lane = (lane & 3) * 2;
#pragma unroll
    for (int i = 0; i < 2; i++) {
#pragma unroll
        for (int j = 0; j < 4; j++) {
            const int row0 = n0 + wrow * 32 + i * 16 + r_lane;
            const int col  = m0 + wcol * 32 + j * 8 + c_lane;
            const size_t idx0 = ((size_t)b * N_ + row0) * M_ + col;
            const size_t idx1 = idx0 + (size_t)8 * M_;
            int2 mk0 = *(const int2*)(mask + idx0);
            int2 mk1 = *(const int2*)(mask + idx1);
            float2 v0, v1;
            v0.x = mk0.x ? acc[i][j][0] : MASK_FILL;
            v0.y = mk0.y ? acc[i][j][1] : MASK_FILL;
            v1.x = mk1.x ? acc[i][j][2] : MASK_FILL;
            v1.y = mk1.y ? acc[i][j][3] : MASK_FILL;
            *(float2*)(attn + idx0) = v0;
            *(float2*)(attn + idx1) = v1;
        }
    }
}

// K3: out = attn @ v. A = attn fp16 splits [N_, M_], B = V^T fp16 [DV_, M_].
__global__ void __launch_bounds__(512) av_mma_kernel(float* __restrict__ out)
{
    extern __shared__ char smem[];
    const uint32_t sb = smem_u32(smem);
    const int tid = threadIdx.x, warp = tid >> 5, lane = tid & 31;
    const int b = blockIdx.z, c0 = blockIdx.x * 128, n0 = blockIdx.y * 128;
    const int wrow = warp >> 2, wcol = warp & 3;

    const __half* srcs[3] = {
        g_ah   + ((size_t)b * N_  + n0) * M_,
        g_al   + ((size_t)b * N_  + n0) * M_,
        g_vt16 + ((size_t)b * DV_ + c0) * M_ };

    float acc[2][4][4];
#pragma unroll
    for (int i = 0; i < 2; i++)
#pragma unroll
        for (int j = 0; j < 4; j++)
#pragma unroll
            for (int r = 0; r < 4; r++) acc[i][j][r] = 0.f;

    gemm_mainloop<M_ / 32>(srcs, M_, sb, tid, wrow, wcol, lane, acc);

    const int r_lane = lane >> 2, c_lane = (lane & 3) * 2;
#pragma unroll
    for (int i = 0; i < 2; i++) {
#pragma unroll
        for (int j = 0; j < 4; j++) {
            const int row0 = n0 + wrow * 32 + i * 16 + r_lane;
            const int col  = c0 + wcol * 32 + j * 8 + c_lane;
            const size_t idx0 = ((size_t)b * N_ + row0) * DV_ + col;
            const size_t idx1 = idx0 + (size_t)8 * DV_;
            *(float2*)(out + idx0) = make_float2(acc[i][j][0], acc[i][j][1]);
            *(float2*)(out + idx1) = make_float2(acc[i][j][2], acc[i][j][3]);
        }
    }
}

// ---------------------------------------------------------------------------
// K2: attn = softmax(logits) + softmax(oa) in place; emit fp16 hi/lo splits.
// ---------------------------------------------------------------------------
__global__ void __launch_bounds__(256) softmax_add_kernel(
    const float* __restrict__ oa, float* __restrict__ attn)
{
    const size_t row = blockIdx.x;
    float*       s = attn + row * M_;
    const float* o = oa   + row * M_;

    const int tid  = threadIdx.x;
    const int lane = tid & 31;
    const int warp = tid >> 5;
    const int base = tid * 8;

    float sv[8], ov[8];
    float4 s0 = ((const float4*)(s + base))[0], s1 = ((const float4*)(s + base))[1];
    float4 o0 = ((const float4*)(o + base))[0], o1 = ((const float4*)(o + base))[1];
    sv[0]=s0.x; sv[1]=s0.y; sv[2]=s0.z; sv[3]=s0.w;
    sv[4]=s1.x; sv[5]=s1.y; sv[6]=s1.z; sv[7]=s1.w;
    ov[0]=o0.x; ov[1]=o0.y; ov[2]=o0.z; ov[3]=o0.w;
    ov[4]=o1.x; ov[5]=o1.y; ov[6]=o1.z; ov[7]=o1.w;

    float smax = -3.4e38f, omax = -3.4e38f;
#pragma unroll
    for (int i = 0; i < 8; i++) { smax = fmaxf(smax, sv[i]); omax = fmaxf(omax, ov[i]); }
#pragma unroll
    for (int off = 16; off > 0; off >>= 1) {
        smax = fmaxf(smax, __shfl_xor_sync(0xffffffffu, smax, off));
        omax = fmaxf(omax, __shfl_xor_sync(0xffffffffu, omax, off));
    }
    __shared__ float red[4][8];
    if (lane == 0) { red[0][warp] = smax; red[1][warp] = omax; }
    __syncthreads();
#pragma unroll
    for (int w = 0; w < 8; w++) { smax = fmaxf(smax, red[0][w]); omax = fmaxf(omax, red[1][w]); }

    float ssum = 0.f, osum = 0.f;
#pragma unroll
    for (int i = 0; i < 8; i++) {
        sv[i] = __expf(sv[i] - smax);
        ov[i] = __expf(ov[i] - omax);
        ssum += sv[i]; osum += ov[i];
    }
#pragma unroll
    for (int off = 16; off > 0; off >>= 1) {
        ssum += __shfl_xor_sync(0xffffffffu, ssum, off);
        osum += __shfl_xor_sync(0xffffffffu, osum, off);
    }
    if (lane == 0) { red[2][warp] = ssum; red[3][warp] = osum; }
    __syncthreads();
    ssum = 0.f; osum = 0.f;
#pragma unroll
    for (int w = 0; w < 8; w++) { ssum += red[2][w]; osum += red[3][w]; }
    const float sinv = 1.0f / ssum;
    const float oinv = 1.0f / osum;

    float vals[8];
    __half h[8], l[8];
#pragma unroll
    for (int i = 0; i < 8; i++) {
        vals[i] = sv[i] * sinv + ov[i] * oinv;
        split2h(vals[i], h[i], l[i]);
    }
    ((float4*)(s + base))[0] = make_float4(vals[0], vals[1], vals[2], vals[3]);
    ((float4*)(s + base))[1] = make_float4(vals[4], vals[5], vals[6], vals[7]);
    __half2* dh = (__half2*)(g_ah + row * M_ + base);
    __half2* dl = (__half2*)(g_al + row * M_ + base);
    dh[0] = {h[0], h[1]}; dh[1] = {h[2], h[3]}; dh[2] = {h[4], h[5]}; dh[3] = {h[6], h[7]};
    dl[0] = {l[0], l[1]}; dl[1] = {l[2], l[3]}; dl[2] = {l[4], l[5]}; dl[3] = {l[6], l[7]};
}

// ---------------------------------------------------------------------------
extern "C" void kernel_launch(void* const* d_in, const int* in_sizes, int n_in,
                              void* d_out, int out_size)
{
    const float* q    = (const float*)d_in[0];
    const float* k    = (const float*)d_in[1];
    const float* v    = (const float*)d_in[2];
    const float* oa   = (const float*)d_in[3];
    const int*   mask = (const int*)d_in[4];
    // d_in[5] = feature; always truthy for these shapes, ignored.

    float* out  = (float*)d_out;                        // [B, N, DV]
    float* attn = out + (size_t)B_ * N_ * DV_;          // [B, N, M]

    cudaFuncSetAttribute(qk_mma_kernel, cudaFuncAttributeMaxDynamicSharedMemorySize, GEMM_SMEM);
    cudaFuncSetAttribute(av_mma_kernel, cudaFuncAttributeMaxDynamicSharedMemorySize, GEMM_SMEM);

    prep_q_kernel<<<(size_t)B_ * N_ * D_ / 4 / 256, 256>>>(q);
    prep_k_kernel<<<(size_t)B_ * M_ * D_ / 4 / 256, 256>>>(k);
    prep_vt_kernel<<<dim3(M_ / 32, DV_ / 32, B_), dim3(32, 8)>>>(v);

    qk_mma_kernel<<<dim3(M_ / 128, N_ / 128, B_), 512, GEMM_SMEM>>>(mask, attn);
    softmax_add_kernel<<<B_ * N_, 256>>>(oa, attn);
    av_mma_kernel<<<dim3(DV_ / 128, N_ / 128, B_), 512, GEMM_SMEM>>>(out);
}

// round 6
// speedup vs baseline: 3.6631x; 1.3703x over previous
#include <cuda_runtime.h>
#include <cuda_fp16.h>
#include <cstdint>

#define B_  8
#define N_  4096
#define M_  2048
#define D_  256
#define DV_ 256
#define INV_T (1.0f / 16.0f)
#define MASK_FILL -1e9f

// ---------------------------------------------------------------------------
// Scratch (__device__ globals; no dynamic allocation allowed).
// ---------------------------------------------------------------------------
__device__ __half g_qh[(size_t)B_ * N_ * D_];
__device__ __half g_ql[(size_t)B_ * N_ * D_];
__device__ __half g_k16[(size_t)B_ * M_ * D_];
__device__ __half g_vt16[(size_t)B_ * DV_ * M_];   // V^T [B, DV, M]
__device__ __half g_a16[(size_t)B_ * N_ * M_];     // attn fp16 for K3

// ---------------------------------------------------------------------------
// Helpers (plain sm_80+ PTX only — tcgen05 is feature-gated off this target).
// ---------------------------------------------------------------------------
__device__ __forceinline__ uint32_t smem_u32(const void* p) {
    uint32_t a;
    asm("{ .reg .u64 t; cvta.to.shared.u64 t, %1; cvt.u32.u64 %0, t; }"
        : "=r"(a) : "l"(p));
    return a;
}

__device__ __forceinline__ void cp16(uint32_t dst, const void* src) {
    asm volatile("cp.async.cg.shared.global [%0], [%1], 16;"
                 :: "r"(dst), "l"(src));
}
#define CP_COMMIT() asm volatile("cp.async.commit_group;" ::: "memory")
#define CP_WAIT(n)  asm volatile("cp.async.wait_group %0;" :: "n"(n) : "memory")

#define LDSM_X4(r0, r1, r2, r3, addr)                                         \
    asm volatile("ldmatrix.sync.aligned.m8n8.x4.shared.b16 {%0,%1,%2,%3}, [%4];" \
                 : "=r"(r0), "=r"(r1), "=r"(r2), "=r"(r3) : "r"(addr))

#define MMA16816(d, a, b)                                                     \
    asm volatile("mma.sync.aligned.m16n8k16.row.col.f32.f16.f16.f32 "         \
                 "{%0,%1,%2,%3}, {%4,%5,%6,%7}, {%8,%9}, {%0,%1,%2,%3};"      \
                 : "+f"((d)[0]), "+f"((d)[1]), "+f"((d)[2]), "+f"((d)[3])     \
                 : "r"((a)[0]), "r"((a)[1]), "r"((a)[2]), "r"((a)[3]),        \
                   "r"((b)[0]), "r"((b)[1]))

// SW64 swizzle for 64-byte rows (32 fp16): conflict-free ldmatrix phases.
__device__ __forceinline__ uint32_t sw64(uint32_t off) {
    return off ^ ((off >> 3) & 0x30);
}

__device__ __forceinline__ void split2h(float x, __half& h, __half& l) {
    h = __float2half(x);
    l = __float2half(x - __half2float(h));
}

// ---------------------------------------------------------------------------
// Prep kernels.
// ---------------------------------------------------------------------------
__global__ void __launch_bounds__(256) prep_q_kernel(const float* __restrict__ q) {
    size_t i = ((size_t)blockIdx.x * 256 + threadIdx.x) * 4;
    float4 x = *(const float4*)(q + i);
    __half h0,l0,h1,l1,h2,l2,h3,l3;
    split2h(x.x * INV_T, h0, l0); split2h(x.y * INV_T, h1, l1);
    split2h(x.z * INV_T, h2, l2); split2h(x.w * INV_T, h3, l3);
    __half2* dh = (__half2*)(g_qh + i);
    __half2* dl = (__half2*)(g_ql + i);
    dh[0] = {h0, h1}; dh[1] = {h2, h3};
    dl[0] = {l0, l1}; dl[1] = {l2, l3};
}

__global__ void __launch_bounds__(256) prep_k_kernel(const float* __restrict__ k) {
    size_t i = ((size_t)blockIdx.x * 256 + threadIdx.x) * 4;
    float4 x = *(const float4*)(k + i);
    __half2* d = (__half2*)(g_k16 + i);
    d[0] = {__float2half(x.x), __float2half(x.y)};
    d[1] = {__float2half(x.z), __float2half(x.w)};
}

__global__ void prep_vt_kernel(const float* __restrict__ v) {
    __shared__ float t[32][33];
    const int b = blockIdx.z, m0 = blockIdx.x * 32, c0 = blockIdx.y * 32;
    for (int j = threadIdx.y; j < 32; j += 8)
        t[j][threadIdx.x] = v[((size_t)b * M_ + m0 + j) * DV_ + c0 + threadIdx.x];
    __syncthreads();
    for (int j = threadIdx.y; j < 32; j += 8) {
        size_t o = ((size_t)b * DV_ + c0 + j) * M_ + m0 + threadIdx.x;
        g_vt16[o] = __float2half(t[threadIdx.x][j]);
    }
}

// ---------------------------------------------------------------------------
// GEMM mainloop: block tile 64x128, 256 threads (8 warps, 2x4, warp 32x32),
// K-chunks of 32, 4-stage cp.async ring.
// Stage layout: NA x A-split (64 rows x 64B = 4KB each) | B (128 x 64B = 8KB).
// NA=2 (qk: q hi/lo), NA=1 (av: attn fp16). Stage = 16KB / 12KB.
// ---------------------------------------------------------------------------
template <int NC, int NA>
__device__ __forceinline__ void gemm_mainloop(
    const __half* const* srcs, const size_t sstride,
    uint32_t sb, int tid, int wrow, int wcol, int lane, float acc[2][4][4])
{
    const uint32_t STAGE = (NA + 2) * 4096u;
    const uint32_t BBASE = NA * 4096u;
    const int NROWS = NA * 64 + 128;

    auto load_stage = [&](int c) {
        const uint32_t stg = sb + (uint32_t)(c & 3) * STAGE;
        const int kt = c * 32;
#pragma unroll
        for (int u0 = 0; u0 < NROWS * 4; u0 += 256) {
            const int u = u0 + tid;
            const int rt = u >> 2, seg = u & 3;
            const __half* src;
            uint32_t base;
            int r;
            if (rt < NA * 64) {
                const int ti = rt >> 6;
                src = srcs[ti]; base = (uint32_t)ti * 4096u; r = rt & 63;
            } else {
                src = srcs[NA]; base = BBASE; r = rt - NA * 64;
            }
            cp16(stg + base + sw64((uint32_t)(r * 64 + seg * 16)),
                 src + (size_t)r * sstride + kt + seg * 8);
        }
        CP_COMMIT();
    };

    load_stage(0);
    if (NC > 1) load_stage(1);
    if (NC > 2) load_stage(2);

    for (int c = 0; c < NC; c++) {
        if (c + 3 <= NC) { CP_WAIT(2); }
        else if (c + 2 == NC) { CP_WAIT(1); }
        else { CP_WAIT(0); }
        __syncthreads();                 // stage c visible; all done with c-1

        const uint32_t stg = sb + (uint32_t)(c & 3) * STAGE;
#pragma unroll
        for (int kk = 0; kk < 2; kk++) {
            uint32_t ah[2][4], al[2][4], bf[4][2];
#pragma unroll
            for (int i = 0; i < 2; i++) {
                uint32_t off = (uint32_t)((wrow * 32 + i * 16 + (lane & 15)) * 64
                                          + ((lane >> 4) * 16) + kk * 32);
                LDSM_X4(ah[i][0], ah[i][1], ah[i][2], ah[i][3], stg + sw64(off));
                if (NA == 2)
                    LDSM_X4(al[i][0], al[i][1], al[i][2], al[i][3],
                            stg + 4096u + sw64(off));
            }
#pragma unroll
            for (int jj = 0; jj < 2; jj++) {
                uint32_t off = (uint32_t)((wcol * 32 + jj * 16 + (lane & 15)) * 64
                                          + ((lane >> 4) * 16) + kk * 32);
                uint32_t r0, r1, r2, r3;
                LDSM_X4(r0, r1, r2, r3, stg + BBASE + sw64(off));
                bf[jj * 2][0] = r0; bf[jj * 2][1] = r2;
                bf[jj * 2 + 1][0] = r1; bf[jj * 2 + 1][1] = r3;
            }
#pragma unroll
            for (int i = 0; i < 2; i++)
#pragma unroll
                for (int j = 0; j < 4; j++) {
                    MMA16816(acc[i][j], ah[i], bf[j]);
                    if (NA == 2) MMA16816(acc[i][j], al[i], bf[j]);
                }
        }
        if (c + 3 < NC) load_stage(c + 3);
    }
}

#define QK_SMEM (4 * 16384)
#define AV_SMEM (4 * 12288)

// K1: logits = mask ? (q/T)@k^T : -1e9.  Block 64(n) x 128(m).
__global__ void __launch_bounds__(256, 3) qk_mma_kernel(
    const int* __restrict__ mask, float* __restrict__ attn)
{
    extern __shared__ char smem[];
    const uint32_t sb = smem_u32(smem);
    const int tid = threadIdx.x, warp = tid >> 5, lane = tid & 31;
    const int b = blockIdx.z, m0 = blockIdx.x * 128, n0 = blockIdx.y * 64;
    const int wrow = warp >> 2, wcol = warp & 3;

    const __half* srcs[3] = {
        g_qh  + ((size_t)b * N_ + n0) * D_,
        g_ql  + ((size_t)b * N_ + n0) * D_,
        g_k16 + ((size_t)b * M_ + m0) * D_ };

    float acc[2][4][4];
#pragma unroll
    for (int i = 0; i < 2; i++)
#pragma unroll
        for (int j = 0; j < 4; j++)
#pragma unroll
            for (int r = 0; r < 4; r++) acc[i][j][r] = 0.f;

    gemm_mainloop<D_ / 32, 2>(srcs, D_, sb, tid, wrow, wcol, lane, acc);

    const int r_lane = lane >> 2, c_lane = (lane & 3) * 2;
#pragma unroll
    for (int i = 0; i < 2; i++) {
#pragma unroll
        for (int j = 0; j < 4; j++) {
            const int row0 = n0 + wrow * 32 + i * 16 + r_lane;
            const int col  = m0 + wcol * 32 + j * 8 + c_lane;
            const size_t idx0 = ((size_t)b * N_ + row0) * M_ + col;
            const size_t idx1 = idx0 + (size_t)8 * M_;
            int2 mk0 = *(const int2*)(mask + idx0);
            int2 mk1 = *(const int2*)(mask + idx1);
            float2 v0, v1;
            v0.x = mk0.x ? acc[i][j][0] : MASK_FILL;
            v0.y = mk0.y ? acc[i][j][1] : MASK_FILL;
            v1.x = mk1.x ? acc[i][j][2] : MASK_FILL;
            v1.y = mk1.y ? acc[i][j][3] : MASK_FILL;
            *(float2*)(attn + idx0) = v0;
            *(float2*)(attn + idx1) = v1;
        }
    }
}

// K3: out = attn @ v.  Block 64(n) x 128(dv), single-fp16 attn operand.
__global__ void __launch_bounds__(256, 3) av_mma_kernel(float* __restrict__ out)
{
    extern __shared__ char smem[];
    const uint32_t sb = smem_u32(smem);
    const int tid = threadIdx.x, warp = tid >> 5, lane = tid & 31;
    const int b = blockIdx.z, c0 = blockIdx.x * 128, n0 = blockIdx.y * 64;
    const int wrow = warp >> 2, wcol = warp & 3;

    const __half* srcs[2] = {
        g_a16  + ((size_t)b * N_  + n0) * M_,
        g_vt16 + ((size_t)b * DV_ + c0) * M_ };

    float acc[2][4][4];
#pragma unroll
    for (int i = 0; i < 2; i++)
#pragma unroll
        for (int j = 0; j < 4; j++)
#pragma unroll
            for (int r = 0; r < 4; r++) acc[i][j][r] = 0.f;

    gemm_mainloop<M_ / 32, 1>(srcs, M_, sb, tid, wrow, wcol, lane, acc);

    const int r_lane = lane >> 2, c_lane = (lane & 3) * 2;
#pragma unroll
    for (int i = 0; i < 2; i++) {
#pragma unroll
        for (int j = 0; j < 4; j++) {
            const int row0 = n0 + wrow * 32 + i * 16 + r_lane;
            const int col  = c0 + wcol * 32 + j * 8 + c_lane;
            const size_t idx0 = ((size_t)b * N_ + row0) * DV_ + col;
            const size_t idx1 = idx0 + (size_t)8 * DV_;
            *(float2*)(out + idx0) = make_float2(acc[i][j][0], acc[i][j][1]);
            *(float2*)(out + idx1) = make_float2(acc[i][j][2], acc[i][j][3]);
        }
    }
}

// ---------------------------------------------------------------------------
// K2: attn = softmax(logits) + softmax(oa) in place; emit fp16 attn copy.
// ---------------------------------------------------------------------------
__global__ void __launch_bounds__(256) softmax_add_kernel(
    const float* __restrict__ oa, float* __restrict__ attn)
{
    const size_t row = blockIdx.x;
    float*       s = attn + row * M_;
    const float* o = oa   + row * M_;

    const int tid  = threadIdx.x;
    const int lane = tid & 31;
    const int warp = tid >> 5;
    const int base = tid * 8;

    float sv[8], ov[8];
    float4 s0 = ((const float4*)(s + base))[0], s1 = ((const float4*)(s + base))[1];
    float4 o0 = ((const float4*)(o + base))[0], o1 = ((const float4*)(o + base))[1];
    sv[0]=s0.x; sv[1]=s0.y; sv[2]=s0.z; sv[3]=s0.w;
    sv[4]=s1.x; sv[5]=s1.y; sv[6]=s1.z; sv[7]=s1.w;
    ov[0]=o0.x; ov[1]=o0.y; ov[2]=o0.z; ov[3]=o0.w;
    ov[4]=o1.x; ov[5]=o1.y; ov[6]=o1.z; ov[7]=o1.w;

    float smax = -3.4e38f, omax = -3.4e38f;
#pragma unroll
    for (int i = 0; i < 8; i++) { smax = fmaxf(smax, sv[i]); omax = fmaxf(omax, ov[i]); }
#pragma unroll
    for (int off = 16; off > 0; off >>= 1) {
        smax = fmaxf(smax, __shfl_xor_sync(0xffffffffu, smax, off));
        omax = fmaxf(omax, __shfl_xor_sync(0xffffffffu, omax, off));
    }
    __shared__ float red[4][8];
    if (lane == 0) { red[0][warp] = smax; red[1][warp] = omax; }
    __syncthreads();
#pragma unroll
    for (int w = 0; w < 8; w++) { smax = fmaxf(smax, red[0][w]); omax = fmaxf(omax, red[1][w]); }

    float ssum = 0.f, osum = 0.f;
#pragma unroll
    for (int i = 0; i < 8; i++) {
        sv[i] = __expf(sv[i] - smax);
        ov[i] = __expf(ov[i] - omax);
        ssum += sv[i]; osum += ov[i];
    }
#pragma unroll
    for (int off = 16; off > 0; off >>= 1) {
        ssum += __shfl_xor_sync(0xffffffffu, ssum, off);
        osum += __shfl_xor_sync(0xffffffffu, osum, off);
    }
    if (lane == 0) { red[2][warp] = ssum; red[3][warp] = osum; }
    __syncthreads();
    ssum = 0.f; osum = 0.f;
#pragma unroll
    for (int w = 0; w < 8; w++) { ssum += red[2][w]; osum += red[3][w]; }
    const float sinv = 1.0f / ssum;
    const float oinv = 1.0f / osum;

    float vals[8];
#pragma unroll
    for (int i = 0; i < 8; i++)
        vals[i] = sv[i] * sinv + ov[i] * oinv;
    ((float4*)(s + base))[0] = make_float4(vals[0], vals[1], vals[2], vals[3]);
    ((float4*)(s + base))[1] = make_float4(vals[4], vals[5], vals[6], vals[7]);
    __half2* dh = (__half2*)(g_a16 + row * M_ + base);
    dh[0] = {__float2half(vals[0]), __float2half(vals[1])};
    dh[1] = {__float2half(vals[2]), __float2half(vals[3])};
    dh[2] = {__float2half(vals[4]), __float2half(vals[5])};
    dh[3] = {__float2half(vals[6]), __float2half(vals[7])};
}

// ---------------------------------------------------------------------------
extern "C" void kernel_launch(void* const* d_in, const int* in_sizes, int n_in,
                              void* d_out, int out_size)
{
    const float* q    = (const float*)d_in[0];
    const float* k    = (const float*)d_in[1];
    const float* v    = (const float*)d_in[2];
    const float* oa   = (const float*)d_in[3];
    const int*   mask = (const int*)d_in[4];
    // d_in[5] = feature; always truthy for these shapes, ignored.

    float* out  = (float*)d_out;                        // [B, N, DV]
    float* attn = out + (size_t)B_ * N_ * DV_;          // [B, N, M]

    cudaFuncSetAttribute(qk_mma_kernel, cudaFuncAttributeMaxDynamicSharedMemorySize, QK_SMEM);
    cudaFuncSetAttribute(av_mma_kernel, cudaFuncAttributeMaxDynamicSharedMemorySize, AV_SMEM);

    prep_q_kernel<<<(size_t)B_ * N_ * D_ / 4 / 256, 256>>>(q);
    prep_k_kernel<<<(size_t)B_ * M_ * D_ / 4 / 256, 256>>>(k);
    prep_vt_kernel<<<dim3(M_ / 32, DV_ / 32, B_), dim3(32, 8)>>>(v);

    qk_mma_kernel<<<dim3(M_ / 128, N_ / 64, B_), 256, QK_SMEM>>>(mask, attn);
    softmax_add_kernel<<<B_ * N_, 256>>>(oa, attn);
    av_mma_kernel<<<dim3(DV_ / 128, N_ / 64, B_), 256, AV_SMEM>>>(out);
}